// round 15
// baseline (speedup 1.0000x reference)
#include <cuda_runtime.h>
#include <cuda_fp16.h>
#include <cstdint>

// Problem shape (fixed by dataset)
#define T_TOK 4096   // B*S
#define DDIM  1024
#define FDIM  4096

// GEMM tiling (halves). BK = 64 halves = 32 words = 128 B/row.
#define BM 128
#define BN 128
#define BKW 32                           // 32-bit words of k per stage-row
#define LDS_PAD 36                       // words per smem row (32 + 4) -> 144 B
#define TILE_WORDS (128 * LDS_PAD)       // 4608 words per operand tile
#define STAGE_WORDS (2 * TILE_WORDS)
#define NSTAGE 3
#define SMEM_BYTES_G (NSTAGE * STAGE_WORDS * 4)   // 110592

// Router staging
#define RT_XW (32 * 36)
#define RT_WW (20 * 36)
#define RT_STG (RT_XW + RT_WW)

// Scratch (static __device__ — no dynamic allocation allowed)
__device__ uint32_t g_xh[(size_t)T_TOK * DDIM / 2];    // x as half2 words, 8 MB
__device__ uint32_t g_wih[(size_t)FDIM * DDIM / 2];    // Wi as half2 words, 8 MB
__device__ uint32_t g_woh[(size_t)DDIM * FDIM / 2];    // Wo as half2 words, 8 MB
__device__ uint32_t g_hcomb[(size_t)T_TOK * FDIM / 2]; // hcomb as half2 words, 32 MB
__device__ float4 g_top[T_TOK];                        // (w1, w2, i1(bits), i2(bits))
__device__ float g_low[T_TOK * 16];

__device__ __forceinline__ uint32_t smem_u32(const void* p) {
    uint32_t a;
    asm("{ .reg .u64 t; cvta.to.shared.u64 t, %1; cvt.u32.u64 %0, t; }" : "=r"(a) : "l"(p));
    return a;
}
__device__ __forceinline__ void mma_f16(float* c, const uint32_t* a, const uint32_t* b) {
    asm volatile("mma.sync.aligned.m16n8k16.row.col.f32.f16.f16.f32 "
                 "{%0,%1,%2,%3}, {%4,%5,%6,%7}, {%8,%9}, {%0,%1,%2,%3};"
                 : "+f"(c[0]), "+f"(c[1]), "+f"(c[2]), "+f"(c[3])
                 : "r"(a[0]), "r"(a[1]), "r"(a[2]), "r"(a[3]), "r"(b[0]), "r"(b[1]));
}
__device__ __forceinline__ void ldm_x4(uint32_t* r, uint32_t addr) {
    asm volatile("ldmatrix.sync.aligned.m8n8.x4.shared.b16 {%0,%1,%2,%3}, [%4];"
                 : "=r"(r[0]), "=r"(r[1]), "=r"(r[2]), "=r"(r[3]) : "r"(addr));
}
__device__ __forceinline__ uint32_t pack_h2(float lo, float hi) {
    __half2 h = __floats2half2_rn(lo, hi);
    return *(uint32_t*)&h;
}

// ---------------------------------------------------------------------------
// fp32 -> half2 conversion (Wi, Wo only; x converted inside the router).
// ---------------------------------------------------------------------------
__global__ __launch_bounds__(256)
void conv_h(const float4* __restrict__ src, uint2* __restrict__ dst, int n4)
{
    int i = blockIdx.x * blockDim.x + threadIdx.x;
    int stride = gridDim.x * blockDim.x;
    for (; i < n4; i += stride) {
        float4 v = src[i];
        dst[i] = make_uint2(pack_h2(v.x, v.y), pack_h2(v.z, v.w));
    }
}

// ---------------------------------------------------------------------------
// Router: 128 blocks x 640 threads, 32 tokens/block, 3-stage cp.async pipe.
// Thread = (token, j), scalar accumulator. Emits g_xh (half2), g_top, g_low.
// ---------------------------------------------------------------------------
__device__ __forceinline__ void rt_issue(uint32_t base, const float* __restrict__ x,
                                         const float* __restrict__ Wg,
                                         const float* __restrict__ A,
                                         int t0, int k0, int tid)
{
    if (tid < 256) {            // x chunk: 32 tokens x 128 B
        int row = tid >> 3, cc = tid & 7;
        uint32_t off = base + (uint32_t)(row * 36 + cc * 4) * 4;
        const void* g = x + (size_t)(t0 + row) * DDIM + k0 + cc * 4;
        asm volatile("cp.async.cg.shared.global [%0], [%1], 16;" :: "r"(off), "l"(g));
    } else if (tid < 416) {     // weight chunk: 20 rows x 128 B
        int i = tid - 256, row = i >> 3, cc = i & 7;
        const float* src = (row < 4) ? (Wg + (size_t)row * DDIM)
                                     : (A + (size_t)(row - 4) * DDIM);
        uint32_t off = base + (uint32_t)RT_XW * 4 + (uint32_t)(row * 36 + cc * 4) * 4;
        asm volatile("cp.async.cg.shared.global [%0], [%1], 16;" :: "r"(off), "l"(src + k0 + cc * 4));
    }
    asm volatile("cp.async.commit_group;");
}

__global__ __launch_bounds__(640)
void router_kernel(const float* __restrict__ x, const float* __restrict__ Wg,
                   const float* __restrict__ bg, const float* __restrict__ A)
{
    __shared__ float sm[3 * RT_STG];
    __shared__ float ps[32 * 20];
    const uint32_t sb = smem_u32(sm);
    const int tid = threadIdx.x;
    const int t0 = blockIdx.x * 32;
    const int tok = tid / 20, j = tid % 20;

    float acc = 0.f;
    const int nChunk = DDIM / 32;

    rt_issue(sb, x, Wg, A, t0, 0, tid);
    rt_issue(sb + RT_STG * 4, x, Wg, A, t0, 32, tid);

    for (int c = 0; c < nChunk; c++) {
        if (c + 2 < nChunk) {
            asm volatile("cp.async.wait_group 1;");
        } else {
            asm volatile("cp.async.wait_group 0;");
        }
        __syncthreads();

        if (c + 2 < nChunk) {
            int wbuf = c + 2; while (wbuf >= 3) wbuf -= 3;
            rt_issue(sb + (uint32_t)(wbuf * RT_STG) * 4, x, Wg, A, t0, (c + 2) * 32, tid);
        }

        int buf = c; while (buf >= 3) buf -= 3;
        const float* xs = sm + buf * RT_STG;
        const float* ws = xs + RT_XW;

#pragma unroll
        for (int k4 = 0; k4 < 8; k4++) {
            float4 xv = *(const float4*)&xs[tok * 36 + k4 * 4];
            float4 wv = *(const float4*)&ws[j * 36 + k4 * 4];
            acc += xv.x * wv.x + xv.y * wv.y + xv.z * wv.z + xv.w * wv.w;
        }

        if (tid < 512) {
            int tk = tid >> 4, h = tid & 15;
            float lo = xs[tk * 36 + h * 2];
            float hi = xs[tk * 36 + h * 2 + 1];
            g_xh[(size_t)(t0 + tk) * (DDIM / 2) + c * 16 + h] = pack_h2(lo, hi);
        }
    }

    ps[tid] = acc;
    __syncthreads();

    if (tid < 32) {
        int t = t0 + tid;
        float l[4];
#pragma unroll
        for (int e = 0; e < 4; e++) l[e] = ps[tid * 20 + e] + bg[e];
        float m = fmaxf(fmaxf(l[0], l[1]), fmaxf(l[2], l[3]));
        float p[4], s = 0.f;
#pragma unroll
        for (int e = 0; e < 4; e++) { p[e] = expf(l[e] - m); s += p[e]; }
        float inv = 1.f / s;
#pragma unroll
        for (int e = 0; e < 4; e++) p[e] *= inv;
        int i1 = 0; float b1 = p[0];
#pragma unroll
        for (int e = 1; e < 4; e++) if (p[e] > b1) { b1 = p[e]; i1 = e; }
        int i2 = -1; float b2 = -1.f;
#pragma unroll
        for (int e = 0; e < 4; e++) if (e != i1 && p[e] > b2) { b2 = p[e]; i2 = e; }
        g_top[t] = make_float4(b1, b2, __int_as_float(i1), __int_as_float(i2));
#pragma unroll
        for (int i = 0; i < 16; i++)
            g_low[t * 16 + i] = ps[tid * 20 + 4 + i];
    }
}

// ---------------------------------------------------------------------------
// FP16 mma.sync m16n8k16 TN GEMM, 3-stage cp.async pipeline, ldmatrix loads
// with B-fragment ping-pong (ldm for ntp+1 issued before MMAs of ntp).
// MODE 0: A=g_xh, B=g_wih, top-2 MoE epilogue -> g_hcomb (epilogue operands
//         prefetched into the dead stage buffer).  MODE 1: -> Cout fp32.
// ---------------------------------------------------------------------------
__device__ __forceinline__ void issue_tile(uint32_t sbaseA, const uint32_t* __restrict__ Ag,
                                           uint32_t sbaseB, const uint32_t* __restrict__ Bg,
                                           int Kw, int k0w, int tid)
{
#pragma unroll
    for (int t = 0; t < 4; t++) {           // 1024 chunks: 128 rows x 8 chunks
        int idx = tid + t * 256;
        int row = idx >> 3, c4 = idx & 7;
        uint32_t off = (uint32_t)(row * LDS_PAD + c4 * 4) * 4;
        const void* ga = Ag + (size_t)row * Kw + k0w + c4 * 4;
        const void* gb = Bg + (size_t)row * Kw + k0w + c4 * 4;
        asm volatile("cp.async.cg.shared.global [%0], [%1], 16;" :: "r"(sbaseA + off), "l"(ga));
        asm volatile("cp.async.cg.shared.global [%0], [%1], 16;" :: "r"(sbaseB + off), "l"(gb));
    }
}

// Epilogue prefetch into dead stage buffer: top 2KB @0, low 8KB @2048, bm 8KB @10240
__device__ __forceinline__ void issue_epi(uint32_t ebase, int m0, int n0,
                                          const float* __restrict__ pBm, int tid)
{
    if (tid < 128) {            // top: 128 x 16B
        const void* g = &g_top[m0 + tid];
        asm volatile("cp.async.cg.shared.global [%0], [%1], 16;"
                     :: "r"(ebase + (uint32_t)tid * 16), "l"(g));
    }
#pragma unroll
    for (int t = 0; t < 2; t++) {   // low: 512 x 16B
        int i = tid + t * 256;
        const void* g = &g_low[(size_t)(m0 + (i >> 2)) * 16 + (i & 3) * 4];
        asm volatile("cp.async.cg.shared.global [%0], [%1], 16;"
                     :: "r"(ebase + 2048u + (uint32_t)i * 16), "l"(g));
    }
#pragma unroll
    for (int t = 0; t < 2; t++) {   // bm: 512 x 16B  (layout [e][128 f][4 r])
        int i = tid + t * 256;
        int e = i >> 7, f = i & 127;
        const void* g = pBm + (size_t)e * (FDIM * 4) + (size_t)(n0 + f) * 4;
        asm volatile("cp.async.cg.shared.global [%0], [%1], 16;"
                     :: "r"(ebase + 10240u + (uint32_t)i * 16), "l"(g));
    }
    asm volatile("cp.async.commit_group;");
}

template <int MODE>
__global__ __launch_bounds__(256, 2)
void gemm_h(const uint32_t* __restrict__ Ain, const uint32_t* __restrict__ Bin,
            float* __restrict__ Cout, int Kw, const float* __restrict__ pBm)
{
    extern __shared__ uint32_t smem[];
    const uint32_t sb = smem_u32(smem);
    const int tid = threadIdx.x;
    const int wid = tid >> 5, lane = tid & 31;
    const int g = lane >> 2, q = lane & 3;
    const int wm = wid & 3, wn = wid >> 2;
    const int m0 = blockIdx.y * BM;
    const int n0 = blockIdx.x * BN;

    const uint32_t* Aptr = Ain + (size_t)m0 * Kw;
    const uint32_t* Bptr = Bin + (size_t)n0 * Kw;

    uint32_t a_base[2];
#pragma unroll
    for (int mt = 0; mt < 2; mt++) {
        int row = wm * 32 + mt * 16 + (lane & 15);
        a_base[mt] = (uint32_t)(row * (LDS_PAD * 4)) + ((lane >> 4) * 16);
    }
    uint32_t b_base[4];
#pragma unroll
    for (int ntp = 0; ntp < 4; ntp++) {
        int nrow = wn * 64 + ntp * 16 + (lane & 7) + ((lane & 16) ? 8 : 0);
        b_base[ntp] = (uint32_t)(TILE_WORDS * 4) + (uint32_t)(nrow * (LDS_PAD * 4))
                    + (((lane >> 3) & 1) * 16);
    }

    float acc[2][8][4];
#pragma unroll
    for (int mt = 0; mt < 2; mt++)
#pragma unroll
        for (int nt = 0; nt < 8; nt++)
#pragma unroll
            for (int e = 0; e < 4; e++) acc[mt][nt][e] = 0.f;

    const int nIter = Kw / BKW;                 // MODE0: 16, MODE1: 64
    const uint32_t ebase = sb + (uint32_t)STAGE_WORDS * 4;   // stage buffer 1

    issue_tile(sb, Aptr, sb + TILE_WORDS * 4, Bptr, Kw, 0, tid);
    asm volatile("cp.async.commit_group;");
    issue_tile(sb + STAGE_WORDS * 4, Aptr, sb + (STAGE_WORDS + TILE_WORDS) * 4, Bptr, Kw, BKW, tid);
    asm volatile("cp.async.commit_group;");

    int buf = 0;
    for (int i = 0; i < nIter; i++) {
        if (i + 1 < nIter) {
            asm volatile("cp.async.wait_group 1;");
        } else {
            asm volatile("cp.async.wait_group 0;");
        }
        __syncthreads();

        if (i + 2 < nIter) {
            int wbuf = buf + 2; if (wbuf >= NSTAGE) wbuf -= NSTAGE;
            uint32_t wb = sb + (uint32_t)(wbuf * STAGE_WORDS) * 4;
            issue_tile(wb, Aptr, wb + TILE_WORDS * 4, Bptr, Kw, (i + 2) * BKW, tid);
            asm volatile("cp.async.commit_group;");
        } else if (MODE == 0 && i + 2 == nIter) {
            // nIter=16: buffer (nIter % 3)=1 is dead; prefetch epilogue operands.
            issue_epi(ebase, m0, n0, pBm, tid);
        }

        const uint32_t sbuf = sb + (uint32_t)(buf * STAGE_WORDS) * 4;
#pragma unroll
        for (int kk = 0; kk < 4; kk++) {
            const uint32_t koff = (uint32_t)(kk * 32);
            uint32_t a[2][4];
            ldm_x4(a[0], sbuf + a_base[0] + koff);
            ldm_x4(a[1], sbuf + a_base[1] + koff);
            // B ping-pong: load ntp+1 fragments before MMAs consuming ntp.
            uint32_t b0[4], b1[4];
            ldm_x4(b0, sbuf + b_base[0] + koff);
#pragma unroll
            for (int ntp = 0; ntp < 4; ntp++) {
                uint32_t* bc = (ntp & 1) ? b1 : b0;
                uint32_t* bn = (ntp & 1) ? b0 : b1;
                if (ntp < 3) ldm_x4(bn, sbuf + b_base[ntp + 1] + koff);
#pragma unroll
                for (int mt = 0; mt < 2; mt++) {
                    mma_f16(acc[mt][2 * ntp],     a[mt], bc);
                    mma_f16(acc[mt][2 * ntp + 1], a[mt], bc + 2);
                }
            }
        }
        if (++buf >= NSTAGE) buf = 0;
    }

    if (MODE == 0) {
        // Top-2 MoE epilogue from prefetched smem (stage buffer 1):
        // h = w1*relu(base + low_{i1}.bm_{i1}) + w2*relu(base + low_{i2}.bm_{i2})
        const float4* top_s = (const float4*)(smem + STAGE_WORDS);
        const float*  low_s = (const float*)(smem + STAGE_WORDS + 512);
        const float*  bm_s  = (const float*)(smem + STAGE_WORDS + 2560);

#pragma unroll
        for (int mt = 0; mt < 2; mt++) {
#pragma unroll
            for (int half = 0; half < 2; half++) {
                int r = wm * 32 + mt * 16 + g + half * 8;     // local row
                float4 tv = top_s[r];
                float w1 = tv.x, w2 = tv.y;
                int i1 = __float_as_int(tv.z), i2 = __float_as_int(tv.w);
                float4 lv1 = *(const float4*)&low_s[r * 16 + i1 * 4];
                float4 lv2 = *(const float4*)&low_s[r * 16 + i2 * 4];
                uint32_t* dst = g_hcomb + (size_t)(m0 + r) * (FDIM / 2) + n0 / 2;
#pragma unroll
                for (int nt = 0; nt < 8; nt++) {
                    int cl = wn * 64 + nt * 8 + 2 * q;        // even column
                    float o[2];
#pragma unroll
                    for (int j = 0; j < 2; j++) {
                        float base = acc[mt][nt][half * 2 + j];
                        int col = cl + j;
                        float4 bm1 = *(const float4*)&bm_s[(i1 * 128 + col) * 4];
                        float4 bm2 = *(const float4*)&bm_s[(i2 * 128 + col) * 4];
                        float lo1 = lv1.x * bm1.x + lv1.y * bm1.y + lv1.z * bm1.z + lv1.w * bm1.w;
                        float lo2 = lv2.x * bm2.x + lv2.y * bm2.y + lv2.z * bm2.z + lv2.w * bm2.w;
                        o[j] = fmaf(w1, fmaxf(base + lo1, 0.f),
                                    w2 * fmaxf(base + lo2, 0.f));
                    }
                    dst[cl >> 1] = pack_h2(o[0], o[1]);
                }
            }
        }
    } else {
#pragma unroll
        for (int mt = 0; mt < 2; mt++) {
#pragma unroll
            for (int half = 0; half < 2; half++) {
                int r = wm * 32 + mt * 16 + g + half * 8;
                float* dst = Cout + (size_t)(m0 + r) * DDIM + n0;
#pragma unroll
                for (int nt = 0; nt < 8; nt++) {
                    int cl = wn * 64 + nt * 8 + 2 * q;
                    *(float2*)(dst + cl) =
                        make_float2(acc[mt][nt][half * 2], acc[mt][nt][half * 2 + 1]);
                }
            }
        }
    }
}

// ---------------------------------------------------------------------------
extern "C" void kernel_launch(void* const* d_in, const int* in_sizes, int n_in,
                              void* d_out, int out_size)
{
    const float* x  = (const float*)d_in[0];
    const float* Wg = (const float*)d_in[1];
    const float* bg = (const float*)d_in[2];
    const float* Wi = (const float*)d_in[3];
    const float* Wo = (const float*)d_in[4];
    const float* A  = (const float*)d_in[5];
    const float* Bm = (const float*)d_in[6];
    float* out = (float*)d_out;

    cudaFuncSetAttribute(gemm_h<0>, cudaFuncAttributeMaxDynamicSharedMemorySize, SMEM_BYTES_G);
    cudaFuncSetAttribute(gemm_h<1>, cudaFuncAttributeMaxDynamicSharedMemorySize, SMEM_BYTES_G);

    uint32_t* xh = nullptr;  cudaGetSymbolAddress((void**)&xh,  g_xh);
    uint32_t* wih = nullptr; cudaGetSymbolAddress((void**)&wih, g_wih);
    uint32_t* woh = nullptr; cudaGetSymbolAddress((void**)&woh, g_woh);
    uint32_t* hc = nullptr;  cudaGetSymbolAddress((void**)&hc,  g_hcomb);

    conv_h<<<1024, 256>>>((const float4*)Wi, (uint2*)wih, FDIM * DDIM / 4);
    conv_h<<<1024, 256>>>((const float4*)Wo, (uint2*)woh, DDIM * FDIM / 4);

    router_kernel<<<T_TOK / 32, 640>>>(x, Wg, bg, A);   // also writes g_xh

    gemm_h<0><<<dim3(FDIM / BN, T_TOK / BM), 256, SMEM_BYTES_G>>>(xh, wih, nullptr, DDIM / 2, Bm);
    gemm_h<1><<<dim3(DDIM / BN, T_TOK / BM), 256, SMEM_BYTES_G>>>(hc, woh, out, FDIM / 2, nullptr);
}